// round 15
// baseline (speedup 1.0000x reference)
#include <cuda_runtime.h>
#include <cuda_bf16.h>
#include <cuda_fp16.h>

#define BB 2
#define MM 4096
#define DD 512
#define HH 8
#define DKK 64

#define KB_STRIDE 36    // 16-bit-pair rows: 32 data words + 4 pad; ldmatrix conflict-free
#define VB_STRIDE 36
#define VST_STRIDE 129  // projV transpose staging (f32), 128 cols + 1 pad

#define ATTN_WORDS (2*64*KB_STRIDE + 2*64*VB_STRIDE)
#define ATTN_SMEM  ((ATTN_WORDS + 64) * 4)                   // + vm[64] = 37120
#define PROJ_SMEM  ((2*128*KB_STRIDE + 2*128*KB_STRIDE) * 4) // 73728

#define ONES16 0x3C003C00u   // f16x2 {1.0, 1.0}

// ---------------- scratch ----------------
__device__ unsigned g_Qb [BB*HH*MM*DKK/2];   // bf16x2 PRE-SCALED Q [b,h,m,dkpair]
__device__ unsigned g_Kb [BB*HH*MM*DKK/2];   // bf16x2 [b,h,key,dkpair]
__device__ unsigned g_Vh [BB*HH*DKK*MM/2];   // fp16x2 [b,h,dk,keypair] (transposed)
__device__ unsigned g_Xq2[BB*MM*DD/2];       // bf16x2 query
__device__ unsigned g_Xk2[BB*MM*DD/2];       // bf16x2 key
__device__ unsigned g_Xv2[BB*MM*DD/2];       // fp16x2 value
__device__ unsigned g_Wq2[DD*DD/2];          // bf16x2 Wq
__device__ unsigned g_Wk2[DD*DD/2];          // bf16x2 Wk
__device__ unsigned g_Wv2[DD*DD/2];          // fp16x2 Wv
__device__ float    g_vpart[64*HH*DKK];      // per-rowtile V column sums [ytile][h][dk]
__device__ int      g_qlen[BB];
__device__ int      g_klen[BB];

// ---------------- helpers ----------------
__device__ __forceinline__ unsigned pack_bf16(float lo, float hi) {
    __nv_bfloat162 h = __floats2bfloat162_rn(lo, hi);
    return *reinterpret_cast<unsigned*>(&h);
}
__device__ __forceinline__ unsigned pack_f16(float lo, float hi) {
    unsigned d;
    asm("cvt.rn.f16x2.f32 %0, %1, %2;" : "=r"(d) : "f"(hi), "f"(lo));
    return d;
}
__device__ __forceinline__ unsigned ex2_f16x2(unsigned x) {
    unsigned d;
    asm("ex2.approx.f16x2 %0, %1;" : "=r"(d) : "r"(x));
    return d;
}
__device__ __forceinline__ void mma_bf16(float* d, const unsigned* a, unsigned b0, unsigned b1) {
    asm("mma.sync.aligned.m16n8k16.row.col.f32.bf16.bf16.f32 "
        "{%0,%1,%2,%3},{%4,%5,%6,%7},{%8,%9},{%0,%1,%2,%3};"
        : "+f"(d[0]), "+f"(d[1]), "+f"(d[2]), "+f"(d[3])
        : "r"(a[0]), "r"(a[1]), "r"(a[2]), "r"(a[3]), "r"(b0), "r"(b1));
}
__device__ __forceinline__ void mma_f16(float* d, const unsigned* a, unsigned b0, unsigned b1) {
    asm("mma.sync.aligned.m16n8k16.row.col.f32.f16.f16.f32 "
        "{%0,%1,%2,%3},{%4,%5,%6,%7},{%8,%9},{%0,%1,%2,%3};"
        : "+f"(d[0]), "+f"(d[1]), "+f"(d[2]), "+f"(d[3])
        : "r"(a[0]), "r"(a[1]), "r"(a[2]), "r"(a[3]), "r"(b0), "r"(b1));
}
__device__ __forceinline__ void ldsm4(unsigned& r0, unsigned& r1, unsigned& r2, unsigned& r3,
                                      unsigned addr) {
    asm volatile("ldmatrix.sync.aligned.m8n8.x4.shared.b16 {%0,%1,%2,%3}, [%4];"
                 : "=r"(r0), "=r"(r1), "=r"(r2), "=r"(r3) : "r"(addr));
}
__device__ __forceinline__ unsigned smem_u32(const void* p) {
    return (unsigned)__cvta_generic_to_shared(p);
}
__device__ __forceinline__ void cp16(unsigned dst, const void* src) {
    asm volatile("cp.async.cg.shared.global [%0], [%1], 16;" :: "r"(dst), "l"(src));
}
__device__ __forceinline__ void cp_commit() { asm volatile("cp.async.commit_group;"); }
__device__ __forceinline__ void cp_wait_all() { asm volatile("cp.async.wait_group 0;"); }

// ---------------- convert + mask lengths, one launch (wider grid for MLP) ----------------
__global__ void convert_kernel(const float* __restrict__ query, const float* __restrict__ key,
                               const float* __restrict__ value, const float* __restrict__ Wq,
                               const float* __restrict__ Wk,    const float* __restrict__ Wv,
                               const void* key_mask, const void* query_mask)
{
    int y = blockIdx.y;
    if (y == 6) {
        int which = blockIdx.x;
        if (which >= 4) return;
        const void* p = (which < 2) ? query_mask : key_mask;
        int b = which & 1;
        const unsigned char* pc = (const unsigned char*)p;
        int mode = (pc[0] == 1 && pc[1] == 1) ? 0 : (pc[0] == 1 ? 1 : 2);
        int t = threadIdx.x;
        int s = 0;
        for (int m = t; m < MM; m += 256) {
            int idx = b * MM + m;
            int v;
            if (mode == 0)      v = (pc[idx] != 0);
            else if (mode == 1) v = (((const int*)p)[idx] != 0);
            else                v = (((const float*)p)[idx] != 0.0f);
            s += v;
        }
        __shared__ int red[256];
        red[t] = s; __syncthreads();
        for (int off = 128; off > 0; off >>= 1) {
            if (t < off) red[t] += red[t + off];
            __syncthreads();
        }
        if (t == 0) {
            if (which < 2) g_qlen[b] = red[0];
            else           g_klen[b] = red[0];
        }
        return;
    }
    const float* src; unsigned* dst; int n; int isbf;
    switch (y) {
        case 0: src = query; dst = g_Xq2; n = BB*MM*DD; isbf = 1; break;
        case 1: src = key;   dst = g_Xk2; n = BB*MM*DD; isbf = 1; break;
        case 2: src = Wq;    dst = g_Wq2; n = DD*DD;    isbf = 1; break;
        case 3: src = Wk;    dst = g_Wk2; n = DD*DD;    isbf = 1; break;
        case 4: src = value; dst = g_Xv2; n = BB*MM*DD; isbf = 0; break;
        default:src = Wv;    dst = g_Wv2; n = DD*DD;    isbf = 0; break;
    }
    int n4 = n >> 2;
    int stride = gridDim.x * blockDim.x;
    for (int i = blockIdx.x * blockDim.x + threadIdx.x; i < n4; i += stride) {
        float4 v = reinterpret_cast<const float4*>(src)[i];
        uint2 u;
        if (isbf) u = make_uint2(pack_bf16(v.x, v.y), pack_bf16(v.z, v.w));
        else      u = make_uint2(pack_f16(v.x, v.y),  pack_f16(v.z, v.w));
        *reinterpret_cast<uint2*>(&dst[2*i]) = u;
    }
}

// ---------------- merged QKV projection: 128x128 tiles (2 heads/CTA), ldmatrix ----------
// z=0: Q (bf16 -> bf16x2 pre-scaled), z=1: K (bf16 -> bf16x2), z=2: V (fp16 -> fp16x2 T).
__global__ void __launch_bounds__(256) proj_kernel(
    const float* __restrict__ bq, const float* __restrict__ bk, const float* __restrict__ bv)
{
    extern __shared__ unsigned sm[];
    unsigned* Xs[2] = { sm,                   sm + 128*KB_STRIDE };
    unsigned* Ws[2] = { sm + 2*128*KB_STRIDE, sm + 3*128*KB_STRIDE };

    int z = blockIdx.z;
    const unsigned* X2 = (z == 0) ? g_Xq2 : (z == 1) ? g_Xk2 : g_Xv2;
    const unsigned* W2 = (z == 0) ? g_Wq2 : (z == 1) ? g_Wk2 : g_Wv2;

    int tid = threadIdx.x;
    int wid = tid >> 5, lane = tid & 31;
    int g = lane >> 2, t4 = lane & 3;
    int lrow = lane & 7;
    int hp = blockIdx.x;                 // head pair: cols [hp*128, hp*128+128)
    int rowTile = blockIdx.y * 128;
    int colTile = hp * 128;
    int bI = rowTile >> 12;

    auto issue = [&](int c, int bi) {
        int w0 = c * 32;
        #pragma unroll
        for (int it = 0; it < 4; it++) {
            int ch = tid + it * 256, rr = ch >> 3, cc = ch & 7;
            cp16(smem_u32(&Xs[bi][rr * KB_STRIDE + cc*4]), &X2[(rowTile + rr) * 256 + w0 + cc*4]);
        }
        #pragma unroll
        for (int it = 0; it < 4; it++) {
            int ch = tid + it * 256, rr = ch >> 3, cc = ch & 7;
            cp16(smem_u32(&Ws[bi][rr * KB_STRIDE + cc*4]), &W2[(colTile + rr) * 256 + w0 + cc*4]);
        }
        cp_commit();
    };

    float acc[16][4];
    #pragma unroll
    for (int nf = 0; nf < 16; nf++)
        #pragma unroll
        for (int i = 0; i < 4; i++) acc[nf][i] = 0.0f;

    int arow = wid * 16 + lrow + ((lane >> 3) & 1) * 8;
    int aword = (lane >> 4) * 4;
    int bword = (lane >> 3) * 4;

    issue(0, 0);
    for (int c = 0; c < 8; c++) {
        cp_wait_all();
        __syncthreads();
        if (c + 1 < 8) issue(c + 1, (c + 1) & 1);
        const unsigned* Xc = Xs[c & 1];
        const unsigned* Wc = Ws[c & 1];

        unsigned a[4][4];
        unsigned abase = smem_u32(&Xc[arow * KB_STRIDE + aword]);
        #pragma unroll
        for (int kc = 0; kc < 4; kc++)
            ldsm4(a[kc][0], a[kc][1], a[kc][2], a[kc][3], abase + kc * 32);

        #pragma unroll
        for (int nf = 0; nf < 16; nf++) {
            unsigned b0, b1, b2, b3, b4, b5, b6, b7;
            unsigned bbase = smem_u32(&Wc[(nf*8 + lrow) * KB_STRIDE + bword]);
            ldsm4(b0, b1, b2, b3, bbase);
            ldsm4(b4, b5, b6, b7, bbase + 64);
            if (z == 2) {
                mma_f16(acc[nf], a[0], b0, b1);
                mma_f16(acc[nf], a[1], b2, b3);
                mma_f16(acc[nf], a[2], b4, b5);
                mma_f16(acc[nf], a[3], b6, b7);
            } else {
                mma_bf16(acc[nf], a[0], b0, b1);
                mma_bf16(acc[nf], a[1], b2, b3);
                mma_bf16(acc[nf], a[2], b4, b5);
                mma_bf16(acc[nf], a[3], b6, b7);
            }
        }
    }

    if (z < 2) {
        const float* bias = z ? bk : bq;
        unsigned* dst = z ? g_Kb : g_Qb;
        // Q pre-scaled by log2e/d_model (same mul-then-bf16rn sequence as in-attn packing)
        const float scl = z ? 1.0f : (1.44269504088896f / (float)DD);
        int row0 = rowTile + wid * 16 + g;
        #pragma unroll
        for (int nf = 0; nf < 16; nf++) {
            int col = nf*8 + 2*t4;                  // 0..127
            int h = hp*2 + (col >> 6);
            int colh = col & 63;
            float bz0 = bias[colTile + col], bz1 = bias[colTile + col + 1];
            float v00 = (acc[nf][0] + bz0) * scl, v01 = (acc[nf][1] + bz1) * scl;
            float v10 = (acc[nf][2] + bz0) * scl, v11 = (acc[nf][3] + bz1) * scl;
            size_t e0 = (((size_t)(bI*HH + h) * MM) + (row0 & 4095)) * DKK + colh;
            size_t e1 = (((size_t)(bI*HH + h) * MM) + ((row0 + 8) & 4095)) * DKK + colh;
            dst[e0 >> 1] = pack_bf16(v00, v01);
            dst[e1 >> 1] = pack_bf16(v10, v11);
        }
    } else {
        // V: stage f32 tile [128][128], write fp16x2 transposed + per-column partial sums
        __syncthreads();
        float* stage = reinterpret_cast<float*>(sm);
        #pragma unroll
        for (int nf = 0; nf < 16; nf++) {
            int col = nf*8 + 2*t4;
            float bz0 = bv[colTile + col], bz1 = bv[colTile + col + 1];
            int lr0 = wid * 16 + g, lr1 = lr0 + 8;
            stage[lr0 * VST_STRIDE + col]     = acc[nf][0] + bz0;
            stage[lr0 * VST_STRIDE + col + 1] = acc[nf][1] + bz1;
            stage[lr1 * VST_STRIDE + col]     = acc[nf][2] + bz0;
            stage[lr1 * VST_STRIDE + col + 1] = acc[nf][3] + bz1;
        }
        __syncthreads();
        if (tid < 128) {
            float s = 0.0f;
            #pragma unroll 8
            for (int r = 0; r < 128; r++) s += stage[r * VST_STRIDE + tid];
            g_vpart[(blockIdx.y * HH + hp*2 + (tid >> 6)) * DKK + (tid & 63)] = s;
        }
        int m0tile = rowTile & 4095;
        #pragma unroll
        for (int it = 0; it < 32; it++) {
            int idx = tid + it * 256;               // 128 cols x 64 keypairs
            int cg = idx >> 6, kp = idx & 63;
            int h = hp*2 + (cg >> 6);
            int cdk = cg & 63;
            float v0 = stage[(2*kp)     * VST_STRIDE + cg];
            float v1 = stage[(2*kp + 1) * VST_STRIDE + cg];
            g_Vh[(((size_t)(bI*HH + h)) * DKK + cdk) * (MM/2) + (m0tile >> 1) + kp] = pack_f16(v0, v1);
        }
    }
}

// ---------------- flash attention: bf16 QK + fp16 PV, ldmatrix, ex2.f16x2, ones-mma lsum --
__global__ void __launch_bounds__(256, 2) attn_kernel(float* __restrict__ out)
{
    extern __shared__ unsigned sm[];
    unsigned* Ksb0 = sm;
    unsigned* Ksb1 = sm + 64*KB_STRIDE;
    unsigned* Vsb0 = sm + 2*64*KB_STRIDE;
    unsigned* Vsb1 = sm + 2*64*KB_STRIDE + 64*VB_STRIDE;
    float*    vmsm = reinterpret_cast<float*>(sm + ATTN_WORDS);   // 64 floats

    int qt = blockIdx.x, h = blockIdx.y, b = blockIdx.z;
    int q0 = qt * 128;
    int tid = threadIdx.x;
    int wid = tid >> 5, lane = tid & 31;
    int g = lane >> 2, t4 = lane & 3;
    int lrow = lane & 7;
    int bword = (lane >> 3) * 4;

    const size_t head_off = ((size_t)(b * HH + h)) * MM * DKK;
    const unsigned* Qg2 = g_Qb + (head_off >> 1);
    const unsigned* Kg2 = g_Kb + (head_off >> 1);
    const unsigned* Vg2 = g_Vh + ((size_t)(b * HH + h)) * DKK * (MM/2);
    int qlen = g_qlen[b], klen = g_klen[b];

    auto issue = [&](int kt, int bufi) {
        int kt0 = kt * 64;
        unsigned* Kd = bufi ? Ksb1 : Ksb0;
        unsigned* Vd = bufi ? Vsb1 : Vsb0;
        #pragma unroll
        for (int c = 0; c < 2; c++) {
            int ch = tid + c * 256;
            int row = ch >> 3, cc = ch & 7;
            cp16(smem_u32(&Kd[row * KB_STRIDE + cc*4]), &Kg2[(kt0 + row) * 32 + cc*4]);
        }
        #pragma unroll
        for (int c = 0; c < 2; c++) {
            int ch = tid + c * 256;
            int row = ch >> 3, cc = ch & 7;
            cp16(smem_u32(&Vd[row * VB_STRIDE + cc*4]),
                 &Vg2[(size_t)row * (MM/2) + (kt0 >> 1) + cc*4]);
        }
        cp_commit();
    };

    // kick off the first K/V tile load ASAP (before vmean reduction / Q LDGs),
    // unless this is a fully-masked tile that never enters the main loop.
    bool fully_masked = (q0 >= qlen);
    if (!fully_masked) issue(0, 0);

    // mean(V) needed only when this tile has rows >= qlen
    if (q0 + 128 > qlen) {
        if (tid < 64) {
            float s = 0.0f;
            const float* vp = g_vpart + h * DKK + tid;
            #pragma unroll 8
            for (int y = 0; y < 32; y++) s += vp[(size_t)(b * 32 + y) * HH * DKK];
            vmsm[tid] = s * (1.0f / MM);
        }
        __syncthreads();
    }

    if (fully_masked) {   // uniform softmax over all keys -> mean(V)
        #pragma unroll
        for (int it = 0; it < 8; it++) {
            int q = tid + it * 256;
            int rr = q >> 4, cq = q & 15;
            float4 v = *reinterpret_cast<const float4*>(&vmsm[4*cq]);
            *reinterpret_cast<float4*>(&out[((size_t)(b * MM + q0 + rr)) * DD + h * DKK + 4*cq]) = v;
        }
        return;
    }

    // Q fragments: direct bf16x2 loads (pre-scaled in proj) — overlap with cp.async above
    unsigned qa[4][4];
    {
        int r0 = q0 + wid * 16 + g, r1 = r0 + 8;
        #pragma unroll
        for (int kc = 0; kc < 4; kc++) {
            qa[kc][0] = Qg2[r0 * 32 + kc*8 + t4];
            qa[kc][1] = Qg2[r1 * 32 + kc*8 + t4];
            qa[kc][2] = Qg2[r0 * 32 + kc*8 + t4 + 4];
            qa[kc][3] = Qg2[r1 * 32 + kc*8 + t4 + 4];
        }
    }

    float O[8][4];
    #pragma unroll
    for (int nf = 0; nf < 8; nf++)
        #pragma unroll
        for (int i = 0; i < 4; i++) O[nf][i] = 0.0f;
    float lsumacc[4] = {0.0f, 0.0f, 0.0f, 0.0f};

    int nkt = (klen + 63) >> 6;

    for (int kt = 0; kt < nkt; kt++) {
        cp_wait_all();
        __syncthreads();
        if (kt + 1 < nkt) issue(kt + 1, (kt + 1) & 1);
        const unsigned* Ks = (kt & 1) ? Ksb1 : Ksb0;
        const unsigned* Vs = (kt & 1) ? Vsb1 : Vsb0;

        // S = Q K^T  (log2-domain; Q pre-scaled) — K frags via ldmatrix.x4
        float s[8][4];
        #pragma unroll
        for (int nf = 0; nf < 8; nf++)
            #pragma unroll
            for (int i = 0; i < 4; i++) s[nf][i] = 0.0f;
        #pragma unroll
        for (int nf = 0; nf < 8; nf++) {
            unsigned b0, b1, b2, b3, b4, b5, b6, b7;
            unsigned kbase = smem_u32(&Ks[(nf*8 + lrow) * KB_STRIDE + bword]);
            ldsm4(b0, b1, b2, b3, kbase);
            ldsm4(b4, b5, b6, b7, kbase + 64);
            mma_bf16(s[nf], qa[0], b0, b1);
            mma_bf16(s[nf], qa[1], b2, b3);
            mma_bf16(s[nf], qa[2], b4, b5);
            mma_bf16(s[nf], qa[3], b6, b7);
        }

        // P = 2^S via f16x2 ex2; outputs are the PV A-frags
        bool tail = (kt == nkt - 1) && (klen & 63);
        unsigned ph[8][2];
        #pragma unroll
        for (int nf = 0; nf < 8; nf++) {
            unsigned lo = ex2_f16x2(pack_f16(s[nf][0], s[nf][1]));
            unsigned hi = ex2_f16x2(pack_f16(s[nf][2], s[nf][3]));
            if (tail) {
                int c0 = kt * 64 + nf*8 + 2*t4;
                unsigned msk = (c0 < klen ? 0x0000FFFFu : 0u) | (c0 + 1 < klen ? 0xFFFF0000u : 0u);
                lo &= msk; hi &= msk;
            }
            ph[nf][0] = lo; ph[nf][1] = hi;
        }

        unsigned pa[4][4];
        #pragma unroll
        for (int kc = 0; kc < 4; kc++) {
            pa[kc][0] = ph[2*kc][0];
            pa[kc][1] = ph[2*kc][1];
            pa[kc][2] = ph[2*kc + 1][0];
            pa[kc][3] = ph[2*kc + 1][1];
        }
        // row sums via ones-MMA (exact f32 accumulation of the f16 P)
        mma_f16(lsumacc, pa[0], ONES16, ONES16);
        mma_f16(lsumacc, pa[1], ONES16, ONES16);
        mma_f16(lsumacc, pa[2], ONES16, ONES16);
        mma_f16(lsumacc, pa[3], ONES16, ONES16);

        // O += P V  — V frags via ldmatrix.x4
        #pragma unroll
        for (int nf = 0; nf < 8; nf++) {
            unsigned b0, b1, b2, b3, b4, b5, b6, b7;
            unsigned vbase = smem_u32(&Vs[(nf*8 + lrow) * VB_STRIDE + bword]);
            ldsm4(b0, b1, b2, b3, vbase);
            ldsm4(b4, b5, b6, b7, vbase + 64);
            mma_f16(O[nf], pa[0], b0, b1);
            mma_f16(O[nf], pa[1], b2, b3);
            mma_f16(O[nf], pa[2], b4, b5);
            mma_f16(O[nf], pa[3], b6, b7);
        }
    }

    // epilogue
    float invl0 = 1.0f / lsumacc[0];
    float invl1 = 1.0f / lsumacc[2];
    int r0 = q0 + wid * 16 + g, r1 = r0 + 8;
    #pragma unroll
    for (int nf = 0; nf < 8; nf++) {
        int col = nf*8 + 2*t4;
        float2 o0, o1;
        if (r0 < qlen) { o0.x = O[nf][0] * invl0; o0.y = O[nf][1] * invl0; }
        else           { o0 = *reinterpret_cast<const float2*>(&vmsm[col]); }
        if (r1 < qlen) { o1.x = O[nf][2] * invl1; o1.y = O[nf][3] * invl1; }
        else           { o1 = *reinterpret_cast<const float2*>(&vmsm[col]); }
        *reinterpret_cast<float2*>(&out[((size_t)(b * MM + r0)) * DD + h * DKK + col]) = o0;
        *reinterpret_cast<float2*>(&out[((size_t)(b * MM + r1)) * DD + h * DKK + col]) = o1;
    }
}

// ---------------- launch ----------------
extern "C" void kernel_launch(void* const* d_in, const int* in_sizes, int n_in,
                              void* d_out, int out_size) {
    const float* key   = (const float*)d_in[0];
    const float* query = (const float*)d_in[1];
    const float* value = (const float*)d_in[2];
    const float* Wq = (const float*)d_in[3];
    const float* bq = (const float*)d_in[4];
    const float* Wk = (const float*)d_in[5];
    const float* bk = (const float*)d_in[6];
    const float* Wv = (const float*)d_in[7];
    const float* bv = (const float*)d_in[8];
    const void* key_mask   = d_in[9];
    const void* query_mask = d_in[10];
    float* out = (float*)d_out;

    cudaFuncSetAttribute(proj_kernel, cudaFuncAttributeMaxDynamicSharedMemorySize, PROJ_SMEM);
    cudaFuncSetAttribute(attn_kernel, cudaFuncAttributeMaxDynamicSharedMemorySize, ATTN_SMEM);

    convert_kernel<<<dim3(512, 7), 256>>>(query, key, value, Wq, Wk, Wv, key_mask, query_mask);
    proj_kernel<<<dim3(4, 64, 3), 256, PROJ_SMEM>>>(bq, bk, bv);
    attn_kernel<<<dim3(MM / 128, HH, BB), 256, ATTN_SMEM>>>(out);
}

// round 16
// speedup vs baseline: 1.0158x; 1.0158x over previous
#include <cuda_runtime.h>
#include <cuda_bf16.h>
#include <cuda_fp16.h>

#define BB 2
#define MM 4096
#define DD 512
#define HH 8
#define DKK 64

#define KB_STRIDE 36    // 16-bit-pair rows: 32 data words + 4 pad; ldmatrix conflict-free
#define VB_STRIDE 36
#define VST_STRIDE 129  // projV transpose staging (f32), 128 cols + 1 pad

#define ATTN_WORDS (2*64*KB_STRIDE + 2*64*VB_STRIDE)
#define ATTN_SMEM  ((ATTN_WORDS + 64) * 4)                   // + vm[64] = 37120
#define PROJ_SMEM  ((2*128*KB_STRIDE + 2*128*KB_STRIDE) * 4) // 73728

#define ONES16 0x3C003C00u   // f16x2 {1.0, 1.0}

// ---------------- scratch ----------------
__device__ unsigned g_Qb [BB*HH*MM*DKK/2];   // bf16x2 PRE-SCALED Q [b,h,m,dkpair]
__device__ unsigned g_Kb [BB*HH*MM*DKK/2];   // bf16x2 [b,h,key,dkpair]
__device__ unsigned g_Vh [BB*HH*DKK*MM/2];   // fp16x2 [b,h,dk,keypair] (transposed)
__device__ unsigned g_Xq2[BB*MM*DD/2];       // bf16x2 query
__device__ unsigned g_Xk2[BB*MM*DD/2];       // bf16x2 key
__device__ unsigned g_Xv2[BB*MM*DD/2];       // fp16x2 value
__device__ unsigned g_Wq2[DD*DD/2];          // bf16x2 Wq
__device__ unsigned g_Wk2[DD*DD/2];          // bf16x2 Wk
__device__ unsigned g_Wv2[DD*DD/2];          // fp16x2 Wv
__device__ float    g_vpart[64*HH*DKK];      // per-rowtile V column sums [ytile][h][dk]
__device__ int      g_qlen[BB];
__device__ int      g_klen[BB];

// ---------------- helpers ----------------
__device__ __forceinline__ unsigned pack_bf16(float lo, float hi) {
    __nv_bfloat162 h = __floats2bfloat162_rn(lo, hi);
    return *reinterpret_cast<unsigned*>(&h);
}
__device__ __forceinline__ unsigned pack_f16(float lo, float hi) {
    unsigned d;
    asm("cvt.rn.f16x2.f32 %0, %1, %2;" : "=r"(d) : "f"(hi), "f"(lo));
    return d;
}
__device__ __forceinline__ unsigned ex2_f16x2(unsigned x) {
    unsigned d;
    asm("ex2.approx.f16x2 %0, %1;" : "=r"(d) : "r"(x));
    return d;
}
__device__ __forceinline__ void mma_bf16(float* d, const unsigned* a, unsigned b0, unsigned b1) {
    asm("mma.sync.aligned.m16n8k16.row.col.f32.bf16.bf16.f32 "
        "{%0,%1,%2,%3},{%4,%5,%6,%7},{%8,%9},{%0,%1,%2,%3};"
        : "+f"(d[0]), "+f"(d[1]), "+f"(d[2]), "+f"(d[3])
        : "r"(a[0]), "r"(a[1]), "r"(a[2]), "r"(a[3]), "r"(b0), "r"(b1));
}
__device__ __forceinline__ void mma_f16(float* d, const unsigned* a, unsigned b0, unsigned b1) {
    asm("mma.sync.aligned.m16n8k16.row.col.f32.f16.f16.f32 "
        "{%0,%1,%2,%3},{%4,%5,%6,%7},{%8,%9},{%0,%1,%2,%3};"
        : "+f"(d[0]), "+f"(d[1]), "+f"(d[2]), "+f"(d[3])
        : "r"(a[0]), "r"(a[1]), "r"(a[2]), "r"(a[3]), "r"(b0), "r"(b1));
}
__device__ __forceinline__ void ldsm4(unsigned& r0, unsigned& r1, unsigned& r2, unsigned& r3,
                                      unsigned addr) {
    asm volatile("ldmatrix.sync.aligned.m8n8.x4.shared.b16 {%0,%1,%2,%3}, [%4];"
                 : "=r"(r0), "=r"(r1), "=r"(r2), "=r"(r3) : "r"(addr));
}
__device__ __forceinline__ unsigned smem_u32(const void* p) {
    return (unsigned)__cvta_generic_to_shared(p);
}
__device__ __forceinline__ void cp16(unsigned dst, const void* src) {
    asm volatile("cp.async.cg.shared.global [%0], [%1], 16;" :: "r"(dst), "l"(src));
}
__device__ __forceinline__ void cp_commit() { asm volatile("cp.async.commit_group;"); }
__device__ __forceinline__ void cp_wait_all() { asm volatile("cp.async.wait_group 0;"); }

// ---------------- convert + mask lengths, one launch ----------------
__global__ void convert_kernel(const float* __restrict__ query, const float* __restrict__ key,
                               const float* __restrict__ value, const float* __restrict__ Wq,
                               const float* __restrict__ Wk,    const float* __restrict__ Wv,
                               const void* key_mask, const void* query_mask)
{
    int y = blockIdx.y;
    if (y == 6) {
        int which = blockIdx.x;
        if (which >= 4) return;
        const void* p = (which < 2) ? query_mask : key_mask;
        int b = which & 1;
        const unsigned char* pc = (const unsigned char*)p;
        int mode = (pc[0] == 1 && pc[1] == 1) ? 0 : (pc[0] == 1 ? 1 : 2);
        int t = threadIdx.x;
        int s = 0;
        for (int m = t; m < MM; m += 256) {
            int idx = b * MM + m;
            int v;
            if (mode == 0)      v = (pc[idx] != 0);
            else if (mode == 1) v = (((const int*)p)[idx] != 0);
            else                v = (((const float*)p)[idx] != 0.0f);
            s += v;
        }
        __shared__ int red[256];
        red[t] = s; __syncthreads();
        for (int off = 128; off > 0; off >>= 1) {
            if (t < off) red[t] += red[t + off];
            __syncthreads();
        }
        if (t == 0) {
            if (which < 2) g_qlen[b] = red[0];
            else           g_klen[b] = red[0];
        }
        return;
    }
    const float* src; unsigned* dst; int n; int isbf;
    switch (y) {
        case 0: src = query; dst = g_Xq2; n = BB*MM*DD; isbf = 1; break;
        case 1: src = key;   dst = g_Xk2; n = BB*MM*DD; isbf = 1; break;
        case 2: src = Wq;    dst = g_Wq2; n = DD*DD;    isbf = 1; break;
        case 3: src = Wk;    dst = g_Wk2; n = DD*DD;    isbf = 1; break;
        case 4: src = value; dst = g_Xv2; n = BB*MM*DD; isbf = 0; break;
        default:src = Wv;    dst = g_Wv2; n = DD*DD;    isbf = 0; break;
    }
    int n4 = n >> 2;
    int stride = gridDim.x * blockDim.x;
    for (int i = blockIdx.x * blockDim.x + threadIdx.x; i < n4; i += stride) {
        float4 v = reinterpret_cast<const float4*>(src)[i];
        uint2 u;
        if (isbf) u = make_uint2(pack_bf16(v.x, v.y), pack_bf16(v.z, v.w));
        else      u = make_uint2(pack_f16(v.x, v.y),  pack_f16(v.z, v.w));
        *reinterpret_cast<uint2*>(&dst[2*i]) = u;
    }
}

// ---------------- merged QKV projection: 128x128 tiles (2 heads/CTA), ldmatrix ----------
// z=0: Q (bf16 -> bf16x2 pre-scaled), z=1: K (bf16 -> bf16x2), z=2: V (fp16 -> fp16x2 T).
__global__ void __launch_bounds__(256) proj_kernel(
    const float* __restrict__ bq, const float* __restrict__ bk, const float* __restrict__ bv)
{
    extern __shared__ unsigned sm[];
    unsigned* Xs[2] = { sm,                   sm + 128*KB_STRIDE };
    unsigned* Ws[2] = { sm + 2*128*KB_STRIDE, sm + 3*128*KB_STRIDE };

    int z = blockIdx.z;
    const unsigned* X2 = (z == 0) ? g_Xq2 : (z == 1) ? g_Xk2 : g_Xv2;
    const unsigned* W2 = (z == 0) ? g_Wq2 : (z == 1) ? g_Wk2 : g_Wv2;

    int tid = threadIdx.x;
    int wid = tid >> 5, lane = tid & 31;
    int g = lane >> 2, t4 = lane & 3;
    int lrow = lane & 7;
    int hp = blockIdx.x;                 // head pair: cols [hp*128, hp*128+128)
    int rowTile = blockIdx.y * 128;
    int colTile = hp * 128;
    int bI = rowTile >> 12;

    auto issue = [&](int c, int bi) {
        int w0 = c * 32;
        #pragma unroll
        for (int it = 0; it < 4; it++) {
            int ch = tid + it * 256, rr = ch >> 3, cc = ch & 7;
            cp16(smem_u32(&Xs[bi][rr * KB_STRIDE + cc*4]), &X2[(rowTile + rr) * 256 + w0 + cc*4]);
        }
        #pragma unroll
        for (int it = 0; it < 4; it++) {
            int ch = tid + it * 256, rr = ch >> 3, cc = ch & 7;
            cp16(smem_u32(&Ws[bi][rr * KB_STRIDE + cc*4]), &W2[(colTile + rr) * 256 + w0 + cc*4]);
        }
        cp_commit();
    };

    float acc[16][4];
    #pragma unroll
    for (int nf = 0; nf < 16; nf++)
        #pragma unroll
        for (int i = 0; i < 4; i++) acc[nf][i] = 0.0f;

    int arow = wid * 16 + lrow + ((lane >> 3) & 1) * 8;
    int aword = (lane >> 4) * 4;
    int bword = (lane >> 3) * 4;

    issue(0, 0);
    for (int c = 0; c < 8; c++) {
        cp_wait_all();
        __syncthreads();
        if (c + 1 < 8) issue(c + 1, (c + 1) & 1);
        const unsigned* Xc = Xs[c & 1];
        const unsigned* Wc = Ws[c & 1];

        unsigned a[4][4];
        unsigned abase = smem_u32(&Xc[arow * KB_STRIDE + aword]);
        #pragma unroll
        for (int kc = 0; kc < 4; kc++)
            ldsm4(a[kc][0], a[kc][1], a[kc][2], a[kc][3], abase + kc * 32);

        #pragma unroll
        for (int nf = 0; nf < 16; nf++) {
            unsigned b0, b1, b2, b3, b4, b5, b6, b7;
            unsigned bbase = smem_u32(&Wc[(nf*8 + lrow) * KB_STRIDE + bword]);
            ldsm4(b0, b1, b2, b3, bbase);
            ldsm4(b4, b5, b6, b7, bbase + 64);
            if (z == 2) {
                mma_f16(acc[nf], a[0], b0, b1);
                mma_f16(acc[nf], a[1], b2, b3);
                mma_f16(acc[nf], a[2], b4, b5);
                mma_f16(acc[nf], a[3], b6, b7);
            } else {
                mma_bf16(acc[nf], a[0], b0, b1);
                mma_bf16(acc[nf], a[1], b2, b3);
                mma_bf16(acc[nf], a[2], b4, b5);
                mma_bf16(acc[nf], a[3], b6, b7);
            }
        }
    }

    if (z < 2) {
        const float* bias = z ? bk : bq;
        unsigned* dst = z ? g_Kb : g_Qb;
        // Q pre-scaled by log2e/d_model (same mul-then-bf16rn sequence as in-attn packing)
        const float scl = z ? 1.0f : (1.44269504088896f / (float)DD);
        int row0 = rowTile + wid * 16 + g;
        #pragma unroll
        for (int nf = 0; nf < 16; nf++) {
            int col = nf*8 + 2*t4;                  // 0..127
            int h = hp*2 + (col >> 6);
            int colh = col & 63;
            float bz0 = bias[colTile + col], bz1 = bias[colTile + col + 1];
            float v00 = (acc[nf][0] + bz0) * scl, v01 = (acc[nf][1] + bz1) * scl;
            float v10 = (acc[nf][2] + bz0) * scl, v11 = (acc[nf][3] + bz1) * scl;
            size_t e0 = (((size_t)(bI*HH + h) * MM) + (row0 & 4095)) * DKK + colh;
            size_t e1 = (((size_t)(bI*HH + h) * MM) + ((row0 + 8) & 4095)) * DKK + colh;
            dst[e0 >> 1] = pack_bf16(v00, v01);
            dst[e1 >> 1] = pack_bf16(v10, v11);
        }
    } else {
        // V: stage f32 tile [128][128], write fp16x2 transposed + per-column partial sums
        __syncthreads();
        float* stage = reinterpret_cast<float*>(sm);
        #pragma unroll
        for (int nf = 0; nf < 16; nf++) {
            int col = nf*8 + 2*t4;
            float bz0 = bv[colTile + col], bz1 = bv[colTile + col + 1];
            int lr0 = wid * 16 + g, lr1 = lr0 + 8;
            stage[lr0 * VST_STRIDE + col]     = acc[nf][0] + bz0;
            stage[lr0 * VST_STRIDE + col + 1] = acc[nf][1] + bz1;
            stage[lr1 * VST_STRIDE + col]     = acc[nf][2] + bz0;
            stage[lr1 * VST_STRIDE + col + 1] = acc[nf][3] + bz1;
        }
        __syncthreads();
        if (tid < 128) {
            float s = 0.0f;
            #pragma unroll 8
            for (int r = 0; r < 128; r++) s += stage[r * VST_STRIDE + tid];
            g_vpart[(blockIdx.y * HH + hp*2 + (tid >> 6)) * DKK + (tid & 63)] = s;
        }
        int m0tile = rowTile & 4095;
        #pragma unroll
        for (int it = 0; it < 32; it++) {
            int idx = tid + it * 256;               // 128 cols x 64 keypairs
            int cg = idx >> 6, kp = idx & 63;
            int h = hp*2 + (cg >> 6);
            int cdk = cg & 63;
            float v0 = stage[(2*kp)     * VST_STRIDE + cg];
            float v1 = stage[(2*kp + 1) * VST_STRIDE + cg];
            g_Vh[(((size_t)(bI*HH + h)) * DKK + cdk) * (MM/2) + (m0tile >> 1) + kp] = pack_f16(v0, v1);
        }
    }
}

// ---------------- flash attention: bf16 QK + fp16 PV, ldmatrix, ex2.f16x2, ones-mma lsum --
__global__ void __launch_bounds__(256, 2) attn_kernel(float* __restrict__ out)
{
    extern __shared__ unsigned sm[];
    unsigned* Ksb0 = sm;
    unsigned* Ksb1 = sm + 64*KB_STRIDE;
    unsigned* Vsb0 = sm + 2*64*KB_STRIDE;
    unsigned* Vsb1 = sm + 2*64*KB_STRIDE + 64*VB_STRIDE;
    float*    vmsm = reinterpret_cast<float*>(sm + ATTN_WORDS);   // 64 floats

    int qt = blockIdx.x, h = blockIdx.y, b = blockIdx.z;
    int q0 = qt * 128;
    int tid = threadIdx.x;
    int wid = tid >> 5, lane = tid & 31;
    int g = lane >> 2, t4 = lane & 3;
    int lrow = lane & 7;
    int bword = (lane >> 3) * 4;

    const size_t head_off = ((size_t)(b * HH + h)) * MM * DKK;
    const unsigned* Qg2 = g_Qb + (head_off >> 1);
    const unsigned* Kg2 = g_Kb + (head_off >> 1);
    const unsigned* Vg2 = g_Vh + ((size_t)(b * HH + h)) * DKK * (MM/2);
    int qlen = g_qlen[b], klen = g_klen[b];

    // mean(V) needed only when this tile has rows >= qlen
    if (q0 + 128 > qlen) {
        if (tid < 64) {
            float s = 0.0f;
            const float* vp = g_vpart + h * DKK + tid;
            #pragma unroll 8
            for (int y = 0; y < 32; y++) s += vp[(size_t)(b * 32 + y) * HH * DKK];
            vmsm[tid] = s * (1.0f / MM);
        }
        __syncthreads();
    }

    if (q0 >= qlen) {     // fully-masked q tile: uniform softmax over all keys -> mean(V)
        #pragma unroll
        for (int it = 0; it < 8; it++) {
            int q = tid + it * 256;
            int rr = q >> 4, cq = q & 15;
            float4 v = *reinterpret_cast<const float4*>(&vmsm[4*cq]);
            *reinterpret_cast<float4*>(&out[((size_t)(b * MM + q0 + rr)) * DD + h * DKK + 4*cq]) = v;
        }
        return;
    }

    auto issue = [&](int kt, int bufi) {
        int kt0 = kt * 64;
        unsigned* Kd = bufi ? Ksb1 : Ksb0;
        unsigned* Vd = bufi ? Vsb1 : Vsb0;
        #pragma unroll
        for (int c = 0; c < 2; c++) {
            int ch = tid + c * 256;
            int row = ch >> 3, cc = ch & 7;
            cp16(smem_u32(&Kd[row * KB_STRIDE + cc*4]), &Kg2[(kt0 + row) * 32 + cc*4]);
        }
        #pragma unroll
        for (int c = 0; c < 2; c++) {
            int ch = tid + c * 256;
            int row = ch >> 3, cc = ch & 7;
            cp16(smem_u32(&Vd[row * VB_STRIDE + cc*4]),
                 &Vg2[(size_t)row * (MM/2) + (kt0 >> 1) + cc*4]);
        }
        cp_commit();
    };

    // Q fragments: direct bf16x2 loads (pre-scaled in proj)
    unsigned qa[4][4];
    {
        int r0 = q0 + wid * 16 + g, r1 = r0 + 8;
        #pragma unroll
        for (int kc = 0; kc < 4; kc++) {
            qa[kc][0] = Qg2[r0 * 32 + kc*8 + t4];
            qa[kc][1] = Qg2[r1 * 32 + kc*8 + t4];
            qa[kc][2] = Qg2[r0 * 32 + kc*8 + t4 + 4];
            qa[kc][3] = Qg2[r1 * 32 + kc*8 + t4 + 4];
        }
    }

    float O[8][4];
    #pragma unroll
    for (int nf = 0; nf < 8; nf++)
        #pragma unroll
        for (int i = 0; i < 4; i++) O[nf][i] = 0.0f;
    float lsumacc[4] = {0.0f, 0.0f, 0.0f, 0.0f};

    int nkt = (klen + 63) >> 6;

    issue(0, 0);
    for (int kt = 0; kt < nkt; kt++) {
        cp_wait_all();
        __syncthreads();
        if (kt + 1 < nkt) issue(kt + 1, (kt + 1) & 1);
        const unsigned* Ks = (kt & 1) ? Ksb1 : Ksb0;
        const unsigned* Vs = (kt & 1) ? Vsb1 : Vsb0;

        // S = Q K^T  (log2-domain; Q pre-scaled) — K frags via ldmatrix.x4
        float s[8][4];
        #pragma unroll
        for (int nf = 0; nf < 8; nf++)
            #pragma unroll
            for (int i = 0; i < 4; i++) s[nf][i] = 0.0f;
        #pragma unroll
        for (int nf = 0; nf < 8; nf++) {
            unsigned b0, b1, b2, b3, b4, b5, b6, b7;
            unsigned kbase = smem_u32(&Ks[(nf*8 + lrow) * KB_STRIDE + bword]);
            ldsm4(b0, b1, b2, b3, kbase);
            ldsm4(b4, b5, b6, b7, kbase + 64);
            mma_bf16(s[nf], qa[0], b0, b1);
            mma_bf16(s[nf], qa[1], b2, b3);
            mma_bf16(s[nf], qa[2], b4, b5);
            mma_bf16(s[nf], qa[3], b6, b7);
        }

        // P = 2^S via f16x2 ex2; outputs are the PV A-frags
        bool tail = (kt == nkt - 1) && (klen & 63);
        unsigned ph[8][2];
        #pragma unroll
        for (int nf = 0; nf < 8; nf++) {
            unsigned lo = ex2_f16x2(pack_f16(s[nf][0], s[nf][1]));
            unsigned hi = ex2_f16x2(pack_f16(s[nf][2], s[nf][3]));
            if (tail) {
                int c0 = kt * 64 + nf*8 + 2*t4;
                unsigned msk = (c0 < klen ? 0x0000FFFFu : 0u) | (c0 + 1 < klen ? 0xFFFF0000u : 0u);
                lo &= msk; hi &= msk;
            }
            ph[nf][0] = lo; ph[nf][1] = hi;
        }

        unsigned pa[4][4];
        #pragma unroll
        for (int kc = 0; kc < 4; kc++) {
            pa[kc][0] = ph[2*kc][0];
            pa[kc][1] = ph[2*kc][1];
            pa[kc][2] = ph[2*kc + 1][0];
            pa[kc][3] = ph[2*kc + 1][1];
        }
        // row sums via ones-MMA (exact f32 accumulation of the f16 P)
        mma_f16(lsumacc, pa[0], ONES16, ONES16);
        mma_f16(lsumacc, pa[1], ONES16, ONES16);
        mma_f16(lsumacc, pa[2], ONES16, ONES16);
        mma_f16(lsumacc, pa[3], ONES16, ONES16);

        // O += P V  — V frags via ldmatrix.x4
        #pragma unroll
        for (int nf = 0; nf < 8; nf++) {
            unsigned b0, b1, b2, b3, b4, b5, b6, b7;
            unsigned vbase = smem_u32(&Vs[(nf*8 + lrow) * VB_STRIDE + bword]);
            ldsm4(b0, b1, b2, b3, vbase);
            ldsm4(b4, b5, b6, b7, vbase + 64);
            mma_f16(O[nf], pa[0], b0, b1);
            mma_f16(O[nf], pa[1], b2, b3);
            mma_f16(O[nf], pa[2], b4, b5);
            mma_f16(O[nf], pa[3], b6, b7);
        }
    }

    // epilogue
    float invl0 = 1.0f / lsumacc[0];
    float invl1 = 1.0f / lsumacc[2];
    int r0 = q0 + wid * 16 + g, r1 = r0 + 8;
    #pragma unroll
    for (int nf = 0; nf < 8; nf++) {
        int col = nf*8 + 2*t4;
        float2 o0, o1;
        if (r0 < qlen) { o0.x = O[nf][0] * invl0; o0.y = O[nf][1] * invl0; }
        else           { o0 = *reinterpret_cast<const float2*>(&vmsm[col]); }
        if (r1 < qlen) { o1.x = O[nf][2] * invl1; o1.y = O[nf][3] * invl1; }
        else           { o1 = *reinterpret_cast<const float2*>(&vmsm[col]); }
        *reinterpret_cast<float2*>(&out[((size_t)(b * MM + r0)) * DD + h * DKK + col]) = o0;
        *reinterpret_cast<float2*>(&out[((size_t)(b * MM + r1)) * DD + h * DKK + col]) = o1;
    }
}

// ---------------- launch ----------------
extern "C" void kernel_launch(void* const* d_in, const int* in_sizes, int n_in,
                              void* d_out, int out_size) {
    const float* key   = (const float*)d_in[0];
    const float* query = (const float*)d_in[1];
    const float* value = (const float*)d_in[2];
    const float* Wq = (const float*)d_in[3];
    const float* bq = (const float*)d_in[4];
    const float* Wk = (const float*)d_in[5];
    const float* bk = (const float*)d_in[6];
    const float* Wv = (const float*)d_in[7];
    const float* bv = (const float*)d_in[8];
    const void* key_mask   = d_in[9];
    const void* query_mask = d_in[10];
    float* out = (float*)d_out;

    cudaFuncSetAttribute(proj_kernel, cudaFuncAttributeMaxDynamicSharedMemorySize, PROJ_SMEM);
    cudaFuncSetAttribute(attn_kernel, cudaFuncAttributeMaxDynamicSharedMemorySize, ATTN_SMEM);

    convert_kernel<<<dim3(256, 7), 256>>>(query, key, value, Wq, Wk, Wv, key_mask, query_mask);
    proj_kernel<<<dim3(4, 64, 3), 256, PROJ_SMEM>>>(bq, bk, bv);
    attn_kernel<<<dim3(MM / 128, HH, BB), 256, ATTN_SMEM>>>(out);
}

// round 17
// speedup vs baseline: 1.1418x; 1.1241x over previous
#include <cuda_runtime.h>
#include <cuda_bf16.h>
#include <cuda_fp16.h>

#define BB 2
#define MM 4096
#define DD 512
#define HH 8
#define DKK 64

#define KB_STRIDE 36    // 16-bit-pair rows: 32 data words + 4 pad; ldmatrix conflict-free
#define VB_STRIDE 36
#define VST_STRIDE 129  // projV transpose staging (f32), 128 cols + 1 pad

#define ATTN_WORDS (2*64*KB_STRIDE + 2*64*VB_STRIDE)
#define ATTN_SMEM  ((ATTN_WORDS + 64) * 4)                   // + vm[64] = 37120
#define PROJ_SMEM  ((2*128*KB_STRIDE + 2*128*KB_STRIDE) * 4) // 73728

#define ONES16 0x3C003C00u   // f16x2 {1.0, 1.0}

// ---------------- scratch ----------------
__device__ unsigned g_Qb [BB*HH*MM*DKK/2];   // bf16x2 PRE-SCALED Q [b,h,m,dkpair]
__device__ unsigned g_Kb [BB*HH*MM*DKK/2];   // bf16x2 [b,h,key,dkpair]
__device__ unsigned g_Vh [BB*HH*DKK*MM/2];   // fp16x2 [b,h,dk,keypair] (transposed)
__device__ unsigned g_Xq2[BB*MM*DD/2];       // bf16x2 query
__device__ unsigned g_Xk2[BB*MM*DD/2];       // bf16x2 key
__device__ unsigned g_Xv2[BB*MM*DD/2];       // fp16x2 value
__device__ unsigned g_Wq2[DD*DD/2];          // bf16x2 Wq
__device__ unsigned g_Wk2[DD*DD/2];          // bf16x2 Wk
__device__ unsigned g_Wv2[DD*DD/2];          // fp16x2 Wv
__device__ float    g_vpart[64*HH*DKK];      // per-rowtile V column sums [ytile][h][dk]
__device__ int      g_qlen[BB];
__device__ int      g_klen[BB];

// ---------------- helpers ----------------
__device__ __forceinline__ unsigned pack_bf16(float lo, float hi) {
    __nv_bfloat162 h = __floats2bfloat162_rn(lo, hi);
    return *reinterpret_cast<unsigned*>(&h);
}
__device__ __forceinline__ unsigned pack_f16(float lo, float hi) {
    unsigned d;
    asm("cvt.rn.f16x2.f32 %0, %1, %2;" : "=r"(d) : "f"(hi), "f"(lo));
    return d;
}
__device__ __forceinline__ unsigned ex2_f16x2(unsigned x) {
    unsigned d;
    asm("ex2.approx.f16x2 %0, %1;" : "=r"(d) : "r"(x));
    return d;
}
__device__ __forceinline__ void mma_bf16(float* d, const unsigned* a, unsigned b0, unsigned b1) {
    asm("mma.sync.aligned.m16n8k16.row.col.f32.bf16.bf16.f32 "
        "{%0,%1,%2,%3},{%4,%5,%6,%7},{%8,%9},{%0,%1,%2,%3};"
        : "+f"(d[0]), "+f"(d[1]), "+f"(d[2]), "+f"(d[3])
        : "r"(a[0]), "r"(a[1]), "r"(a[2]), "r"(a[3]), "r"(b0), "r"(b1));
}
__device__ __forceinline__ void mma_f16(float* d, const unsigned* a, unsigned b0, unsigned b1) {
    asm("mma.sync.aligned.m16n8k16.row.col.f32.f16.f16.f32 "
        "{%0,%1,%2,%3},{%4,%5,%6,%7},{%8,%9},{%0,%1,%2,%3};"
        : "+f"(d[0]), "+f"(d[1]), "+f"(d[2]), "+f"(d[3])
        : "r"(a[0]), "r"(a[1]), "r"(a[2]), "r"(a[3]), "r"(b0), "r"(b1));
}
__device__ __forceinline__ void ldsm4(unsigned& r0, unsigned& r1, unsigned& r2, unsigned& r3,
                                      unsigned addr) {
    asm volatile("ldmatrix.sync.aligned.m8n8.x4.shared.b16 {%0,%1,%2,%3}, [%4];"
                 : "=r"(r0), "=r"(r1), "=r"(r2), "=r"(r3) : "r"(addr));
}
__device__ __forceinline__ unsigned smem_u32(const void* p) {
    return (unsigned)__cvta_generic_to_shared(p);
}
__device__ __forceinline__ void cp16(unsigned dst, const void* src) {
    asm volatile("cp.async.cg.shared.global [%0], [%1], 16;" :: "r"(dst), "l"(src));
}
__device__ __forceinline__ void cp_commit() { asm volatile("cp.async.commit_group;"); }
__device__ __forceinline__ void cp_wait_all() { asm volatile("cp.async.wait_group 0;"); }

// ---------------- convert + mask lengths, one launch ----------------
__global__ void convert_kernel(const float* __restrict__ query, const float* __restrict__ key,
                               const float* __restrict__ value, const float* __restrict__ Wq,
                               const float* __restrict__ Wk,    const float* __restrict__ Wv,
                               const void* key_mask, const void* query_mask)
{
    int y = blockIdx.y;
    if (y == 6) {
        int which = blockIdx.x;
        if (which >= 4) return;
        const void* p = (which < 2) ? query_mask : key_mask;
        int b = which & 1;
        const unsigned char* pc = (const unsigned char*)p;
        int mode = (pc[0] == 1 && pc[1] == 1) ? 0 : (pc[0] == 1 ? 1 : 2);
        int t = threadIdx.x;
        int s = 0;
        for (int m = t; m < MM; m += 256) {
            int idx = b * MM + m;
            int v;
            if (mode == 0)      v = (pc[idx] != 0);
            else if (mode == 1) v = (((const int*)p)[idx] != 0);
            else                v = (((const float*)p)[idx] != 0.0f);
            s += v;
        }
        __shared__ int red[256];
        red[t] = s; __syncthreads();
        for (int off = 128; off > 0; off >>= 1) {
            if (t < off) red[t] += red[t + off];
            __syncthreads();
        }
        if (t == 0) {
            if (which < 2) g_qlen[b] = red[0];
            else           g_klen[b] = red[0];
        }
        return;
    }
    const float* src; unsigned* dst; int n; int isbf;
    switch (y) {
        case 0: src = query; dst = g_Xq2; n = BB*MM*DD; isbf = 1; break;
        case 1: src = key;   dst = g_Xk2; n = BB*MM*DD; isbf = 1; break;
        case 2: src = Wq;    dst = g_Wq2; n = DD*DD;    isbf = 1; break;
        case 3: src = Wk;    dst = g_Wk2; n = DD*DD;    isbf = 1; break;
        case 4: src = value; dst = g_Xv2; n = BB*MM*DD; isbf = 0; break;
        default:src = Wv;    dst = g_Wv2; n = DD*DD;    isbf = 0; break;
    }
    int n4 = n >> 2;
    int stride = gridDim.x * blockDim.x;
    for (int i = blockIdx.x * blockDim.x + threadIdx.x; i < n4; i += stride) {
        float4 v = reinterpret_cast<const float4*>(src)[i];
        uint2 u;
        if (isbf) u = make_uint2(pack_bf16(v.x, v.y), pack_bf16(v.z, v.w));
        else      u = make_uint2(pack_f16(v.x, v.y),  pack_f16(v.z, v.w));
        *reinterpret_cast<uint2*>(&dst[2*i]) = u;
    }
}

// ---------------- merged QKV projection: 128x128 tiles (2 heads/CTA), ldmatrix ----------
// z=0: Q (bf16 -> bf16x2 pre-scaled), z=1: K (bf16 -> bf16x2), z=2: V (fp16 -> fp16x2 T).
// Dead-tile elimination: Q rows >= qlen and K rows >= klen are never consumed by attn
// (fully-masked q-tiles output mean(V); straddling tiles are row-aligned with proj tiles,
// and attn reads K rows < ceil(klen/64)*64 <= any skipped tile's rowTile), so skip them.
__global__ void __launch_bounds__(256) proj_kernel(
    const float* __restrict__ bq, const float* __restrict__ bk, const float* __restrict__ bv)
{
    extern __shared__ unsigned sm[];
    unsigned* Xs[2] = { sm,                   sm + 128*KB_STRIDE };
    unsigned* Ws[2] = { sm + 2*128*KB_STRIDE, sm + 3*128*KB_STRIDE };

    int z = blockIdx.z;
    int rowTile = blockIdx.y * 128;
    int bI = rowTile >> 12;
    int rloc = rowTile & 4095;
    if (z == 0 && rloc >= g_qlen[bI]) return;   // dead Q tile
    if (z == 1 && rloc >= g_klen[bI]) return;   // dead K tile

    const unsigned* X2 = (z == 0) ? g_Xq2 : (z == 1) ? g_Xk2 : g_Xv2;
    const unsigned* W2 = (z == 0) ? g_Wq2 : (z == 1) ? g_Wk2 : g_Wv2;

    int tid = threadIdx.x;
    int wid = tid >> 5, lane = tid & 31;
    int g = lane >> 2, t4 = lane & 3;
    int lrow = lane & 7;
    int hp = blockIdx.x;                 // head pair: cols [hp*128, hp*128+128)
    int colTile = hp * 128;

    auto issue = [&](int c, int bi) {
        int w0 = c * 32;
        #pragma unroll
        for (int it = 0; it < 4; it++) {
            int ch = tid + it * 256, rr = ch >> 3, cc = ch & 7;
            cp16(smem_u32(&Xs[bi][rr * KB_STRIDE + cc*4]), &X2[(rowTile + rr) * 256 + w0 + cc*4]);
        }
        #pragma unroll
        for (int it = 0; it < 4; it++) {
            int ch = tid + it * 256, rr = ch >> 3, cc = ch & 7;
            cp16(smem_u32(&Ws[bi][rr * KB_STRIDE + cc*4]), &W2[(colTile + rr) * 256 + w0 + cc*4]);
        }
        cp_commit();
    };

    float acc[16][4];
    #pragma unroll
    for (int nf = 0; nf < 16; nf++)
        #pragma unroll
        for (int i = 0; i < 4; i++) acc[nf][i] = 0.0f;

    int arow = wid * 16 + lrow + ((lane >> 3) & 1) * 8;
    int aword = (lane >> 4) * 4;
    int bword = (lane >> 3) * 4;

    issue(0, 0);
    for (int c = 0; c < 8; c++) {
        cp_wait_all();
        __syncthreads();
        if (c + 1 < 8) issue(c + 1, (c + 1) & 1);
        const unsigned* Xc = Xs[c & 1];
        const unsigned* Wc = Ws[c & 1];

        unsigned a[4][4];
        unsigned abase = smem_u32(&Xc[arow * KB_STRIDE + aword]);
        #pragma unroll
        for (int kc = 0; kc < 4; kc++)
            ldsm4(a[kc][0], a[kc][1], a[kc][2], a[kc][3], abase + kc * 32);

        #pragma unroll
        for (int nf = 0; nf < 16; nf++) {
            unsigned b0, b1, b2, b3, b4, b5, b6, b7;
            unsigned bbase = smem_u32(&Wc[(nf*8 + lrow) * KB_STRIDE + bword]);
            ldsm4(b0, b1, b2, b3, bbase);
            ldsm4(b4, b5, b6, b7, bbase + 64);
            if (z == 2) {
                mma_f16(acc[nf], a[0], b0, b1);
                mma_f16(acc[nf], a[1], b2, b3);
                mma_f16(acc[nf], a[2], b4, b5);
                mma_f16(acc[nf], a[3], b6, b7);
            } else {
                mma_bf16(acc[nf], a[0], b0, b1);
                mma_bf16(acc[nf], a[1], b2, b3);
                mma_bf16(acc[nf], a[2], b4, b5);
                mma_bf16(acc[nf], a[3], b6, b7);
            }
        }
    }

    if (z < 2) {
        const float* bias = z ? bk : bq;
        unsigned* dst = z ? g_Kb : g_Qb;
        // Q pre-scaled by log2e/d_model (same mul-then-bf16rn sequence as in-attn packing)
        const float scl = z ? 1.0f : (1.44269504088896f / (float)DD);
        int row0 = rowTile + wid * 16 + g;
        #pragma unroll
        for (int nf = 0; nf < 16; nf++) {
            int col = nf*8 + 2*t4;                  // 0..127
            int h = hp*2 + (col >> 6);
            int colh = col & 63;
            float bz0 = bias[colTile + col], bz1 = bias[colTile + col + 1];
            float v00 = (acc[nf][0] + bz0) * scl, v01 = (acc[nf][1] + bz1) * scl;
            float v10 = (acc[nf][2] + bz0) * scl, v11 = (acc[nf][3] + bz1) * scl;
            size_t e0 = (((size_t)(bI*HH + h) * MM) + (row0 & 4095)) * DKK + colh;
            size_t e1 = (((size_t)(bI*HH + h) * MM) + ((row0 + 8) & 4095)) * DKK + colh;
            dst[e0 >> 1] = pack_bf16(v00, v01);
            dst[e1 >> 1] = pack_bf16(v10, v11);
        }
    } else {
        // V: stage f32 tile [128][128], write fp16x2 transposed + per-column partial sums
        __syncthreads();
        float* stage = reinterpret_cast<float*>(sm);
        #pragma unroll
        for (int nf = 0; nf < 16; nf++) {
            int col = nf*8 + 2*t4;
            float bz0 = bv[colTile + col], bz1 = bv[colTile + col + 1];
            int lr0 = wid * 16 + g, lr1 = lr0 + 8;
            stage[lr0 * VST_STRIDE + col]     = acc[nf][0] + bz0;
            stage[lr0 * VST_STRIDE + col + 1] = acc[nf][1] + bz1;
            stage[lr1 * VST_STRIDE + col]     = acc[nf][2] + bz0;
            stage[lr1 * VST_STRIDE + col + 1] = acc[nf][3] + bz1;
        }
        __syncthreads();
        if (tid < 128) {
            float s = 0.0f;
            #pragma unroll 8
            for (int r = 0; r < 128; r++) s += stage[r * VST_STRIDE + tid];
            g_vpart[(blockIdx.y * HH + hp*2 + (tid >> 6)) * DKK + (tid & 63)] = s;
        }
        int m0tile = rowTile & 4095;
        #pragma unroll
        for (int it = 0; it < 32; it++) {
            int idx = tid + it * 256;               // 128 cols x 64 keypairs
            int cg = idx >> 6, kp = idx & 63;
            int h = hp*2 + (cg >> 6);
            int cdk = cg & 63;
            float v0 = stage[(2*kp)     * VST_STRIDE + cg];
            float v1 = stage[(2*kp + 1) * VST_STRIDE + cg];
            g_Vh[(((size_t)(bI*HH + h)) * DKK + cdk) * (MM/2) + (m0tile >> 1) + kp] = pack_f16(v0, v1);
        }
    }
}

// ---------------- flash attention: bf16 QK + fp16 PV, ldmatrix, ex2.f16x2, ones-mma lsum --
__global__ void __launch_bounds__(256, 2) attn_kernel(float* __restrict__ out)
{
    extern __shared__ unsigned sm[];
    unsigned* Ksb0 = sm;
    unsigned* Ksb1 = sm + 64*KB_STRIDE;
    unsigned* Vsb0 = sm + 2*64*KB_STRIDE;
    unsigned* Vsb1 = sm + 2*64*KB_STRIDE + 64*VB_STRIDE;
    float*    vmsm = reinterpret_cast<float*>(sm + ATTN_WORDS);   // 64 floats

    int qt = blockIdx.x, h = blockIdx.y, b = blockIdx.z;
    int q0 = qt * 128;
    int tid = threadIdx.x;
    int wid = tid >> 5, lane = tid & 31;
    int g = lane >> 2, t4 = lane & 3;
    int lrow = lane & 7;
    int bword = (lane >> 3) * 4;

    const size_t head_off = ((size_t)(b * HH + h)) * MM * DKK;
    const unsigned* Qg2 = g_Qb + (head_off >> 1);
    const unsigned* Kg2 = g_Kb + (head_off >> 1);
    const unsigned* Vg2 = g_Vh + ((size_t)(b * HH + h)) * DKK * (MM/2);
    int qlen = g_qlen[b], klen = g_klen[b];

    // mean(V) needed only when this tile has rows >= qlen
    if (q0 + 128 > qlen) {
        if (tid < 64) {
            float s = 0.0f;
            const float* vp = g_vpart + h * DKK + tid;
            #pragma unroll 8
            for (int y = 0; y < 32; y++) s += vp[(size_t)(b * 32 + y) * HH * DKK];
            vmsm[tid] = s * (1.0f / MM);
        }
        __syncthreads();
    }

    if (q0 >= qlen) {     // fully-masked q tile: uniform softmax over all keys -> mean(V)
        #pragma unroll
        for (int it = 0; it < 8; it++) {
            int q = tid + it * 256;
            int rr = q >> 4, cq = q & 15;
            float4 v = *reinterpret_cast<const float4*>(&vmsm[4*cq]);
            *reinterpret_cast<float4*>(&out[((size_t)(b * MM + q0 + rr)) * DD + h * DKK + 4*cq]) = v;
        }
        return;
    }

    auto issue = [&](int kt, int bufi) {
        int kt0 = kt * 64;
        unsigned* Kd = bufi ? Ksb1 : Ksb0;
        unsigned* Vd = bufi ? Vsb1 : Vsb0;
        #pragma unroll
        for (int c = 0; c < 2; c++) {
            int ch = tid + c * 256;
            int row = ch >> 3, cc = ch & 7;
            cp16(smem_u32(&Kd[row * KB_STRIDE + cc*4]), &Kg2[(kt0 + row) * 32 + cc*4]);
        }
        #pragma unroll
        for (int c = 0; c < 2; c++) {
            int ch = tid + c * 256;
            int row = ch >> 3, cc = ch & 7;
            cp16(smem_u32(&Vd[row * VB_STRIDE + cc*4]),
                 &Vg2[(size_t)row * (MM/2) + (kt0 >> 1) + cc*4]);
        }
        cp_commit();
    };

    // Q fragments: direct bf16x2 loads (pre-scaled in proj)
    unsigned qa[4][4];
    {
        int r0 = q0 + wid * 16 + g, r1 = r0 + 8;
        #pragma unroll
        for (int kc = 0; kc < 4; kc++) {
            qa[kc][0] = Qg2[r0 * 32 + kc*8 + t4];
            qa[kc][1] = Qg2[r1 * 32 + kc*8 + t4];
            qa[kc][2] = Qg2[r0 * 32 + kc*8 + t4 + 4];
            qa[kc][3] = Qg2[r1 * 32 + kc*8 + t4 + 4];
        }
    }

    float O[8][4];
    #pragma unroll
    for (int nf = 0; nf < 8; nf++)
        #pragma unroll
        for (int i = 0; i < 4; i++) O[nf][i] = 0.0f;
    float lsumacc[4] = {0.0f, 0.0f, 0.0f, 0.0f};

    int nkt = (klen + 63) >> 6;

    issue(0, 0);
    for (int kt = 0; kt < nkt; kt++) {
        cp_wait_all();
        __syncthreads();
        if (kt + 1 < nkt) issue(kt + 1, (kt + 1) & 1);
        const unsigned* Ks = (kt & 1) ? Ksb1 : Ksb0;
        const unsigned* Vs = (kt & 1) ? Vsb1 : Vsb0;

        // S = Q K^T  (log2-domain; Q pre-scaled) — K frags via ldmatrix.x4
        float s[8][4];
        #pragma unroll
        for (int nf = 0; nf < 8; nf++)
            #pragma unroll
            for (int i = 0; i < 4; i++) s[nf][i] = 0.0f;
        #pragma unroll
        for (int nf = 0; nf < 8; nf++) {
            unsigned b0, b1, b2, b3, b4, b5, b6, b7;
            unsigned kbase = smem_u32(&Ks[(nf*8 + lrow) * KB_STRIDE + bword]);
            ldsm4(b0, b1, b2, b3, kbase);
            ldsm4(b4, b5, b6, b7, kbase + 64);
            mma_bf16(s[nf], qa[0], b0, b1);
            mma_bf16(s[nf], qa[1], b2, b3);
            mma_bf16(s[nf], qa[2], b4, b5);
            mma_bf16(s[nf], qa[3], b6, b7);
        }

        // P = 2^S via f16x2 ex2; outputs are the PV A-frags
        bool tail = (kt == nkt - 1) && (klen & 63);
        unsigned ph[8][2];
        #pragma unroll
        for (int nf = 0; nf < 8; nf++) {
            unsigned lo = ex2_f16x2(pack_f16(s[nf][0], s[nf][1]));
            unsigned hi = ex2_f16x2(pack_f16(s[nf][2], s[nf][3]));
            if (tail) {
                int c0 = kt * 64 + nf*8 + 2*t4;
                unsigned msk = (c0 < klen ? 0x0000FFFFu : 0u) | (c0 + 1 < klen ? 0xFFFF0000u : 0u);
                lo &= msk; hi &= msk;
            }
            ph[nf][0] = lo; ph[nf][1] = hi;
        }

        unsigned pa[4][4];
        #pragma unroll
        for (int kc = 0; kc < 4; kc++) {
            pa[kc][0] = ph[2*kc][0];
            pa[kc][1] = ph[2*kc][1];
            pa[kc][2] = ph[2*kc + 1][0];
            pa[kc][3] = ph[2*kc + 1][1];
        }
        // row sums via ones-MMA (exact f32 accumulation of the f16 P)
        mma_f16(lsumacc, pa[0], ONES16, ONES16);
        mma_f16(lsumacc, pa[1], ONES16, ONES16);
        mma_f16(lsumacc, pa[2], ONES16, ONES16);
        mma_f16(lsumacc, pa[3], ONES16, ONES16);

        // O += P V  — V frags via ldmatrix.x4
        #pragma unroll
        for (int nf = 0; nf < 8; nf++) {
            unsigned b0, b1, b2, b3, b4, b5, b6, b7;
            unsigned vbase = smem_u32(&Vs[(nf*8 + lrow) * VB_STRIDE + bword]);
            ldsm4(b0, b1, b2, b3, vbase);
            ldsm4(b4, b5, b6, b7, vbase + 64);
            mma_f16(O[nf], pa[0], b0, b1);
            mma_f16(O[nf], pa[1], b2, b3);
            mma_f16(O[nf], pa[2], b4, b5);
            mma_f16(O[nf], pa[3], b6, b7);
        }
    }

    // epilogue
    float invl0 = 1.0f / lsumacc[0];
    float invl1 = 1.0f / lsumacc[2];
    int r0 = q0 + wid * 16 + g, r1 = r0 + 8;
    #pragma unroll
    for (int nf = 0; nf < 8; nf++) {
        int col = nf*8 + 2*t4;
        float2 o0, o1;
        if (r0 < qlen) { o0.x = O[nf][0] * invl0; o0.y = O[nf][1] * invl0; }
        else           { o0 = *reinterpret_cast<const float2*>(&vmsm[col]); }
        if (r1 < qlen) { o1.x = O[nf][2] * invl1; o1.y = O[nf][3] * invl1; }
        else           { o1 = *reinterpret_cast<const float2*>(&vmsm[col]); }
        *reinterpret_cast<float2*>(&out[((size_t)(b * MM + r0)) * DD + h * DKK + col]) = o0;
        *reinterpret_cast<float2*>(&out[((size_t)(b * MM + r1)) * DD + h * DKK + col]) = o1;
    }
}

// ---------------- launch ----------------
extern "C" void kernel_launch(void* const* d_in, const int* in_sizes, int n_in,
                              void* d_out, int out_size) {
    const float* key   = (const float*)d_in[0];
    const float* query = (const float*)d_in[1];
    const float* value = (const float*)d_in[2];
    const float* Wq = (const float*)d_in[3];
    const float* bq = (const float*)d_in[4];
    const float* Wk = (const float*)d_in[5];
    const float* bk = (const float*)d_in[6];
    const float* Wv = (const float*)d_in[7];
    const float* bv = (const float*)d_in[8];
    const void* key_mask   = d_in[9];
    const void* query_mask = d_in[10];
    float* out = (float*)d_out;

    cudaFuncSetAttribute(proj_kernel, cudaFuncAttributeMaxDynamicSharedMemorySize, PROJ_SMEM);
    cudaFuncSetAttribute(attn_kernel, cudaFuncAttributeMaxDynamicSharedMemorySize, ATTN_SMEM);

    convert_kernel<<<dim3(256, 7), 256>>>(query, key, value, Wq, Wk, Wv, key_mask, query_mask);
    proj_kernel<<<dim3(4, 64, 3), 256, PROJ_SMEM>>>(bq, bk, bv);
    attn_kernel<<<dim3(MM / 128, HH, BB), 256, ATTN_SMEM>>>(out);
}